// round 8
// baseline (speedup 1.0000x reference)
#include <cuda_runtime.h>
#include <cuda_bf16.h>
#include <mma.h>

using namespace nvcuda;

// ---------------------------------------------------------------------------
// Problem constants
// ---------------------------------------------------------------------------
#define D_MODEL 4096
#define TOK     4096          // B*S = 64*64
#define KE      12288         // 3*D_MODEL (split-bf16 extended K)
#define NQKV    12288         // q|k|v concatenated output features

// ---------------------------------------------------------------------------
// Device scratch (static allocation: harness forbids cudaMalloc)
// ---------------------------------------------------------------------------
__device__ __align__(16) __nv_bfloat16 g_Xext [TOK * KE];                 //  96 MB  [hi|hi|lo]
__device__ __align__(16) __nv_bfloat16 g_Wqkv [NQKV * KE];                // 288 MB  [hi|lo|hi]
__device__ __align__(16) __nv_bfloat16 g_Wo   [D_MODEL * KE];             //  96 MB  [hi|lo|hi]
__device__ __align__(16) float         g_QKV  [TOK * NQKV];               // 192 MB
__device__ __align__(16) __nv_bfloat16 g_Attext[TOK * KE];                //  96 MB  [hi|hi|lo]

// ---------------------------------------------------------------------------
// Conversion kernels: fp32 -> split bf16 (hi + lo) extended-K layout
//   A side (activations): seg0=hi, seg1=hi, seg2=lo
//   B side (weights):     seg0=hi, seg1=lo, seg2=hi
//   => A.B over KE = Ah*Bh + Ah*Bl + Al*Bh  (drops only eps^2 term ~4e-6)
// ---------------------------------------------------------------------------
__global__ void conv_x_kernel(const float* __restrict__ x) {
    int i = blockIdx.x * blockDim.x + threadIdx.x;      // 0 .. TOK*D_MODEL-1
    int m = i >> 12, k = i & 4095;
    float v = x[i];
    __nv_bfloat16 hi = __float2bfloat16(v);
    __nv_bfloat16 lo = __float2bfloat16(v - __bfloat162float(hi));
    size_t base = (size_t)m * KE + k;
    g_Xext[base]        = hi;
    g_Xext[base + 4096] = hi;
    g_Xext[base + 8192] = lo;
}

__global__ void conv_wqkv_kernel(const float* __restrict__ wq,
                                 const float* __restrict__ wk,
                                 const float* __restrict__ wv) {
    int i = blockIdx.x * blockDim.x + threadIdx.x;      // 0 .. 3*2^24-1
    int sel = i >> 24;                                  // which matrix
    int j   = i & 0xFFFFFF;                             // element within matrix
    const float* w = (sel == 0) ? wq : (sel == 1) ? wk : wv;
    float v = w[j];
    __nv_bfloat16 hi = __float2bfloat16(v);
    __nv_bfloat16 lo = __float2bfloat16(v - __bfloat162float(hi));
    int n = j >> 12, k = j & 4095;
    size_t base = (size_t)(sel * 4096 + n) * KE + k;
    g_Wqkv[base]        = hi;
    g_Wqkv[base + 4096] = lo;
    g_Wqkv[base + 8192] = hi;
}

__global__ void conv_wo_kernel(const float* __restrict__ wo) {
    int i = blockIdx.x * blockDim.x + threadIdx.x;
    int n = i >> 12, k = i & 4095;
    float v = wo[i];
    __nv_bfloat16 hi = __float2bfloat16(v);
    __nv_bfloat16 lo = __float2bfloat16(v - __bfloat162float(hi));
    size_t base = (size_t)n * KE + k;
    g_Wo[base]        = hi;
    g_Wo[base + 4096] = lo;
    g_Wo[base + 8192] = hi;
}

// ---------------------------------------------------------------------------
// wmma bf16 GEMM core: C[M][N] = A[M][K] * B[N][K]^T   (both K-contiguous)
// CTA tile 128x128, BK=32, 8 warps (2x4), warp tile 64x32 (4x2 wmma frags).
// Register-prefetch + double-buffered smem. GROUP_M=16 rasterization.
// ---------------------------------------------------------------------------
__device__ __forceinline__ void gemm_core(const __nv_bfloat16* __restrict__ A,
                                          const __nv_bfloat16* __restrict__ B,
                                          float* __restrict__ C,
                                          int Mdim, int Ndim, int Kdim) {
    __shared__ __align__(16) __nv_bfloat16 As[2][128][40];
    __shared__ __align__(16) __nv_bfloat16 Bs[2][128][40];

    const int tid  = threadIdx.x;
    const int warp = tid >> 5;
    const int wm   = warp & 1;          // 0..1  (row group of 64)
    const int wn   = warp >> 1;         // 0..3  (col group of 32)

    // --- grouped rasterization (GROUP along M keeps B panels hot in L2) ---
    const int num_m = Mdim >> 7, num_n = Ndim >> 7;
    const int GROUP = 16;
    int per   = GROUP * num_n;
    int gid   = blockIdx.x / per;
    int rem   = blockIdx.x % per;
    int first = gid * GROUP;
    int gsz   = min(GROUP, num_m - first);
    int pm    = first + rem % gsz;
    int pn    = rem / gsz;
    const int row0 = pm << 7, col0 = pn << 7;

    // --- global load assignment: 128 rows x 4 uint4 per matrix, 2 per thread
    const int lr = tid >> 2;            // 0..63
    const int lc = tid & 3;             // 0..3

    const __nv_bfloat16* pA0 = A + (size_t)(row0 + lr) * Kdim + lc * 8;
    const __nv_bfloat16* pA1 = pA0 + (size_t)64 * Kdim;
    const __nv_bfloat16* pB0 = B + (size_t)(col0 + lr) * Kdim + lc * 8;
    const __nv_bfloat16* pB1 = pB0 + (size_t)64 * Kdim;

    wmma::fragment<wmma::accumulator, 16, 16, 16, float> acc[4][2];
#pragma unroll
    for (int i = 0; i < 4; i++)
#pragma unroll
        for (int j = 0; j < 2; j++) wmma::fill_fragment(acc[i][j], 0.0f);

    // preload tile 0
    uint4 a0 = *(const uint4*)pA0;
    uint4 a1 = *(const uint4*)pA1;
    uint4 b0 = *(const uint4*)pB0;
    uint4 b1 = *(const uint4*)pB1;
    *(uint4*)&As[0][lr][lc * 8]      = a0;
    *(uint4*)&As[0][lr + 64][lc * 8] = a1;
    *(uint4*)&Bs[0][lr][lc * 8]      = b0;
    *(uint4*)&Bs[0][lr + 64][lc * 8] = b1;
    __syncthreads();

    const int niter = Kdim >> 5;
    int buf = 0;
    for (int kt = 0; kt < niter; ++kt) {
        const bool pref = (kt + 1 < niter);
        if (pref) {
            pA0 += 32; pA1 += 32; pB0 += 32; pB1 += 32;
            a0 = *(const uint4*)pA0;
            a1 = *(const uint4*)pA1;
            b0 = *(const uint4*)pB0;
            b1 = *(const uint4*)pB1;
        }
#pragma unroll
        for (int ks = 0; ks < 2; ++ks) {
            wmma::fragment<wmma::matrix_a, 16, 16, 16, __nv_bfloat16, wmma::row_major> af[4];
            wmma::fragment<wmma::matrix_b, 16, 16, 16, __nv_bfloat16, wmma::col_major> bf[2];
#pragma unroll
            for (int i = 0; i < 4; i++)
                wmma::load_matrix_sync(af[i], &As[buf][wm * 64 + i * 16][ks * 16], 40);
#pragma unroll
            for (int j = 0; j < 2; j++)
                wmma::load_matrix_sync(bf[j], &Bs[buf][wn * 32 + j * 16][ks * 16], 40);
#pragma unroll
            for (int i = 0; i < 4; i++)
#pragma unroll
                for (int j = 0; j < 2; j++)
                    wmma::mma_sync(acc[i][j], af[i], bf[j], acc[i][j]);
        }
        if (pref) {
            *(uint4*)&As[buf ^ 1][lr][lc * 8]      = a0;
            *(uint4*)&As[buf ^ 1][lr + 64][lc * 8] = a1;
            *(uint4*)&Bs[buf ^ 1][lr][lc * 8]      = b0;
            *(uint4*)&Bs[buf ^ 1][lr + 64][lc * 8] = b1;
        }
        __syncthreads();
        buf ^= 1;
    }

#pragma unroll
    for (int i = 0; i < 4; i++)
#pragma unroll
        for (int j = 0; j < 2; j++) {
            float* cp = C + (size_t)(row0 + wm * 64 + i * 16) * Ndim + col0 + wn * 32 + j * 16;
            wmma::store_matrix_sync(cp, acc[i][j], Ndim, wmma::mem_row_major);
        }
}

__global__ __launch_bounds__(256, 2) void gemm1_kernel() {
    gemm_core(g_Xext, g_Wqkv, g_QKV, TOK, NQKV, KE);
}
__global__ __launch_bounds__(256, 2) void gemm2_kernel(float* __restrict__ out) {
    gemm_core(g_Attext, g_Wo, out, TOK, D_MODEL, KE);
}

// ---------------------------------------------------------------------------
// Bias + quirky RoPE on QKV (in place).
// Quirk (faithful to the reference broadcasting bug): the rotation position is
// the BATCH index b, inv_freq indexed by m = s*32 + d/2, pairs (d, d+1), d even.
// ---------------------------------------------------------------------------
__global__ void bias_rope_kernel(const float* __restrict__ bq,
                                 const float* __restrict__ bk,
                                 const float* __restrict__ bv) {
    int idx = blockIdx.x * blockDim.x + threadIdx.x;    // TOK * 6144 slots (2 cols each)
    int m = idx / 6144;
    int t = idx - m * 6144;
    int n = t << 1;                                     // even column
    size_t off = (size_t)m * NQKV + n;
    float re = g_QKV[off], im = g_QKV[off + 1];
    if (n < 4096)       { re += bq[n];        im += bq[n + 1]; }
    else if (n < 8192)  { re += bk[n - 4096]; im += bk[n - 4095]; }
    else                { re += bv[n - 8192]; im += bv[n - 8191]; }
    if (n < 8192) {                                     // rope on q and k only
        int d  = n & 63;                                // even
        int s  = m & 63;
        int b  = m >> 6;
        int mp = s * 32 + (d >> 1);
        // inv_freq[mp] = 10000^(-mp/2048) = 2^(-mp * log2(10000)/2048)
        float invf = exp2f(-(float)mp * (13.287712379549449f / 2048.0f));
        float th = (float)b * invf;
        float sn, cs;
        sincosf(th, &sn, &cs);
        float rr = re * cs - im * sn;
        float ri = re * sn + im * cs;
        re = rr; im = ri;
    }
    g_QKV[off]     = re;
    g_QKV[off + 1] = im;
}

// ---------------------------------------------------------------------------
// Attention: one CTA per (b,h). 64x64 tiles, fp32, smem softmax.
// Epilogue writes merged-head output directly in ext bf16 [hi|hi|lo] layout.
// ---------------------------------------------------------------------------
__global__ __launch_bounds__(256) void attn_kernel() {
    __shared__ __align__(16) float bufA[64][68];   // Q -> V -> O
    __shared__ __align__(16) float bufB[64][68];   // K -> S (exp weights)
    __shared__ float red1[256];
    __shared__ float red2[256];

    const int tid = threadIdx.x;
    const int bh  = blockIdx.x;
    const int b   = bh >> 6, h = bh & 63;
    const int rowbase = b << 6;
    const size_t qoff = (size_t)rowbase * NQKV + (h << 6);

    // load Q and K tiles (64x64 f32 each)
#pragma unroll
    for (int it = 0; it < 4; ++it) {
        int i = tid + it * 256;
        int r = i >> 4, seg = i & 15;
        *(float4*)&bufA[r][seg * 4] = *(const float4*)&g_QKV[qoff + (size_t)r * NQKV + seg * 4];
        *(float4*)&bufB[r][seg * 4] = *(const float4*)&g_QKV[qoff + 4096 + (size_t)r * NQKV + seg * 4];
    }
    __syncthreads();

    const int r  = tid & 63;   // q row
    const int cg = tid >> 6;   // col group (16 cols)

    float acc[16];
#pragma unroll
    for (int c = 0; c < 16; c++) acc[c] = 0.0f;
    for (int d4 = 0; d4 < 16; ++d4) {
        float4 qv = *(float4*)&bufA[r][d4 * 4];
#pragma unroll
        for (int c = 0; c < 16; c++) {
            float4 kv = *(float4*)&bufB[cg * 16 + c][d4 * 4];
            acc[c] += qv.x * kv.x + qv.y * kv.y + qv.z * kv.z + qv.w * kv.w;
        }
    }
    __syncthreads();   // everyone done reading Q(bufA) / K(bufB)

    // scale + local max; load V into bufA (Q dead)
    float lm = -1e30f;
#pragma unroll
    for (int c = 0; c < 16; c++) { acc[c] *= 0.125f; lm = fmaxf(lm, acc[c]); }
    red1[r * 4 + cg] = lm;
#pragma unroll
    for (int it = 0; it < 4; ++it) {
        int i = tid + it * 256;
        int rr = i >> 4, seg = i & 15;
        *(float4*)&bufA[rr][seg * 4] =
            *(const float4*)&g_QKV[qoff + 8192 + (size_t)rr * NQKV + seg * 4];
    }
    __syncthreads();

    float rmax = fmaxf(fmaxf(red1[r * 4 + 0], red1[r * 4 + 1]),
                       fmaxf(red1[r * 4 + 2], red1[r * 4 + 3]));
    float ls = 0.0f;
#pragma unroll
    for (int c = 0; c < 16; c++) {
        float e = __expf(acc[c] - rmax);
        bufB[r][cg * 16 + c] = e;      // S (unnormalized weights)
        ls += e;
    }
    red2[r * 4 + cg] = ls;
    __syncthreads();
    float inv = 1.0f / (red2[r * 4 + 0] + red2[r * 4 + 1] + red2[r * 4 + 2] + red2[r * 4 + 3]);

    // PV: out[r][cg*16 + i] = inv * sum_k S[r][k] * V[k][c]
    float o[16];
#pragma unroll
    for (int c = 0; c < 16; c++) o[c] = 0.0f;
#pragma unroll 8
    for (int k = 0; k < 64; k++) {
        float p = bufB[r][k];
        float4 v0 = *(float4*)&bufA[k][cg * 16 + 0];
        float4 v1 = *(float4*)&bufA[k][cg * 16 + 4];
        float4 v2 = *(float4*)&bufA[k][cg * 16 + 8];
        float4 v3 = *(float4*)&bufA[k][cg * 16 + 12];
        o[0] += p * v0.x;  o[1] += p * v0.y;  o[2]  += p * v0.z;  o[3]  += p * v0.w;
        o[4] += p * v1.x;  o[5] += p * v1.y;  o[6]  += p * v1.z;  o[7]  += p * v1.w;
        o[8] += p * v2.x;  o[9] += p * v2.y;  o[10] += p * v2.z;  o[11] += p * v2.w;
        o[12]+= p * v3.x;  o[13]+= p * v3.y;  o[14] += p * v3.z;  o[15] += p * v3.w;
    }
    __syncthreads();   // all done reading V(bufA)
#pragma unroll
    for (int c = 0; c < 16; c++) bufA[r][cg * 16 + c] = o[c] * inv;
    __syncthreads();

    // vectorized hi/hi/lo epilogue into g_Attext (merged-head layout)
    {
        int rr = tid >> 2, seg = tid & 3;           // 64 rows x 4 segs of 16
        const float* src = &bufA[rr][seg * 16];
        __align__(16) __nv_bfloat16 hi[16];
        __align__(16) __nv_bfloat16 lo[16];
#pragma unroll
        for (int t = 0; t < 16; t++) {
            float v = src[t];
            __nv_bfloat16 hh = __float2bfloat16(v);
            hi[t] = hh;
            lo[t] = __float2bfloat16(v - __bfloat162float(hh));
        }
        size_t base = (size_t)(rowbase + rr) * KE + (h << 6) + seg * 16;
        const uint4* ph = (const uint4*)hi;
        const uint4* pl = (const uint4*)lo;
        *(uint4*)&g_Attext[base]           = ph[0];
        *(uint4*)&g_Attext[base + 8]       = ph[1];
        *(uint4*)&g_Attext[base + 4096]    = ph[0];
        *(uint4*)&g_Attext[base + 4104]    = ph[1];
        *(uint4*)&g_Attext[base + 8192]    = pl[0];
        *(uint4*)&g_Attext[base + 8200]    = pl[1];
    }
}

// ---------------------------------------------------------------------------
// Final bias add on the output projection
// ---------------------------------------------------------------------------
__global__ void bias_out_kernel(const float* __restrict__ bo, float* __restrict__ out) {
    int i = blockIdx.x * blockDim.x + threadIdx.x;
    out[i] += bo[i & 4095];
}

// ---------------------------------------------------------------------------
// Launch
// ---------------------------------------------------------------------------
extern "C" void kernel_launch(void* const* d_in, const int* in_sizes, int n_in,
                              void* d_out, int out_size) {
    const float* x  = (const float*)d_in[0];
    const float* wq = (const float*)d_in[1];
    const float* bq = (const float*)d_in[2];
    const float* wk = (const float*)d_in[3];
    const float* bk = (const float*)d_in[4];
    const float* wv = (const float*)d_in[5];
    const float* bv = (const float*)d_in[6];
    const float* wo = (const float*)d_in[7];
    const float* bo = (const float*)d_in[8];
    float* out = (float*)d_out;

    conv_x_kernel   <<<65536, 256>>>(x);
    conv_wqkv_kernel<<<196608, 256>>>(wq, wk, wv);
    conv_wo_kernel  <<<65536, 256>>>(wo);
    gemm1_kernel    <<<3072, 256>>>();
    bias_rope_kernel<<<98304, 256>>>(bq, bk, bv);
    attn_kernel     <<<4096, 256>>>();
    gemm2_kernel    <<<1024, 256>>>(out);
    bias_out_kernel <<<65536, 256>>>(bo, out);
}

// round 13
// speedup vs baseline: 1.1781x; 1.1781x over previous
#include <cuda_runtime.h>
#include <cuda_bf16.h>
#include <mma.h>
#include <cstdint>

using namespace nvcuda;

// ---------------------------------------------------------------------------
// Problem constants
// ---------------------------------------------------------------------------
#define D_MODEL 4096
#define TOK     4096          // B*S = 64*64
#define KE      12288         // 3*D_MODEL (split-bf16 extended K)
#define NQKV    12288         // q|k|v concatenated output features

// ---------------------------------------------------------------------------
// Device scratch (static allocation: harness forbids cudaMalloc)
// ---------------------------------------------------------------------------
__device__ __align__(16) __nv_bfloat16 g_Xext [TOK * KE];                 //  96 MB  [hi|hi|lo]
__device__ __align__(16) __nv_bfloat16 g_Wqkv [NQKV * KE];                // 288 MB  [hi|lo|hi]
__device__ __align__(16) __nv_bfloat16 g_Wo   [D_MODEL * KE];             //  96 MB  [hi|lo|hi]
__device__ __align__(16) float         g_QKV  [TOK * NQKV];               // 192 MB
__device__ __align__(16) __nv_bfloat16 g_Attext[TOK * KE];                //  96 MB  [hi|hi|lo]
__device__ __align__(16) float2        g_rope [64 * 2048];                //   1 MB  cos/sin table

// ---------------------------------------------------------------------------
// cp.async helpers (Ampere+ — compiles fine under compute_103)
// ---------------------------------------------------------------------------
__device__ __forceinline__ unsigned smem_u32(const void* p) {
    unsigned a;
    asm("{ .reg .u64 t; cvta.to.shared.u64 t, %1; cvt.u32.u64 %0, t; }"
        : "=r"(a) : "l"(p));
    return a;
}
#define CP_ASYNC16(dst, src) asm volatile("cp.async.cg.shared.global [%0], [%1], 16;" :: "r"(dst), "l"(src))
#define CP_COMMIT()          asm volatile("cp.async.commit_group;" ::: "memory")
#define CP_WAIT(n)           asm volatile("cp.async.wait_group %0;" :: "n"(n) : "memory")

// ---------------------------------------------------------------------------
// Conversion kernels: fp32 -> split bf16 (hi + lo) extended-K layout
//   A side: [hi|hi|lo], B side: [hi|lo|hi]  => AhBh + AhBl + AlBh
// ---------------------------------------------------------------------------
__global__ void conv_x_kernel(const float* __restrict__ x) {
    int i = blockIdx.x * blockDim.x + threadIdx.x;
    int m = i >> 12, k = i & 4095;
    float v = x[i];
    __nv_bfloat16 hi = __float2bfloat16(v);
    __nv_bfloat16 lo = __float2bfloat16(v - __bfloat162float(hi));
    size_t base = (size_t)m * KE + k;
    g_Xext[base]        = hi;
    g_Xext[base + 4096] = hi;
    g_Xext[base + 8192] = lo;
}

__global__ void conv_wqkv_kernel(const float* __restrict__ wq,
                                 const float* __restrict__ wk,
                                 const float* __restrict__ wv) {
    int i = blockIdx.x * blockDim.x + threadIdx.x;
    int sel = i >> 24;
    int j   = i & 0xFFFFFF;
    const float* w = (sel == 0) ? wq : (sel == 1) ? wk : wv;
    float v = w[j];
    __nv_bfloat16 hi = __float2bfloat16(v);
    __nv_bfloat16 lo = __float2bfloat16(v - __bfloat162float(hi));
    int n = j >> 12, k = j & 4095;
    size_t base = (size_t)(sel * 4096 + n) * KE + k;
    g_Wqkv[base]        = hi;
    g_Wqkv[base + 4096] = lo;
    g_Wqkv[base + 8192] = hi;
}

__global__ void conv_wo_kernel(const float* __restrict__ wo) {
    int i = blockIdx.x * blockDim.x + threadIdx.x;
    int n = i >> 12, k = i & 4095;
    float v = wo[i];
    __nv_bfloat16 hi = __float2bfloat16(v);
    __nv_bfloat16 lo = __float2bfloat16(v - __bfloat162float(hi));
    size_t base = (size_t)n * KE + k;
    g_Wo[base]        = hi;
    g_Wo[base + 4096] = lo;
    g_Wo[base + 8192] = hi;
}

// ---------------------------------------------------------------------------
// Rope table: theta(b, mp) = b * 10000^(-mp/2048);  g_rope = (cos, sin)
// ---------------------------------------------------------------------------
__global__ void rope_init_kernel() {
    int i  = blockIdx.x * blockDim.x + threadIdx.x;   // 131072
    int b  = i >> 11, mp = i & 2047;
    float invf = exp2f(-(float)mp * (13.287712379549449f / 2048.0f));
    float sn, cs;
    sincosf((float)b * invf, &sn, &cs);
    g_rope[i] = make_float2(cs, sn);
}

// ---------------------------------------------------------------------------
// wmma bf16 GEMM: C[M][N] = A[M][K]*B[N][K]^T, fp32 acc.
// CTA tile 128x256, BK=64, 3-stage cp.async pipeline, 8 warps each 64x64
// (4x4 m16n16k16 frags -> 0.5 LDSM loads per mma).
// mode 1: fused bias + table-rope (QKV);  mode 0: fused bias (out proj).
// ---------------------------------------------------------------------------
#define BM 128
#define BN 256
#define BK 64
#define ASTRIDE 72                               // padded row: 72 bf16 = 144 B
#define A_BYTES (BM * ASTRIDE * 2)               // 18432
#define B_BYTES (BN * ASTRIDE * 2)               // 36864
#define STAGE_BYTES (A_BYTES + B_BYTES)          // 55296
#define NST 3
#define SMEM_DYN (NST * STAGE_BYTES)             // 165888 (162 KB)
#define CSTRIDE 260                              // fp32 epilogue buffer stride

__device__ __forceinline__ void gemm_core(
    const __nv_bfloat16* __restrict__ A, const __nv_bfloat16* __restrict__ B,
    float* __restrict__ C, int Mdim, int Ndim, int mode,
    const float* __restrict__ b0p, const float* __restrict__ b1p,
    const float* __restrict__ b2p)
{
    extern __shared__ char dsm[];
    const unsigned sb = smem_u32(dsm);
    const int tid  = threadIdx.x;
    const int warp = tid >> 5;
    const int wm   = warp & 1;          // 0..1 : 64-row group
    const int wn   = warp >> 1;         // 0..3 : 64-col group

    // grouped rasterization along M (keeps B panels hot in L2)
    const int num_n = Ndim >> 8;
    const int num_m = Mdim >> 7;
    const int GROUP = 16;
    int per   = GROUP * num_n;
    int gid   = blockIdx.x / per;
    int rem   = blockIdx.x % per;
    int first = gid * GROUP;
    int gsz   = min(GROUP, num_m - first);
    int pm    = first + rem % gsz;
    int pn    = rem / gsz;
    const int row0 = pm << 7, col0 = pn << 8;

    // cp.async mapping: thread owns col-chunk lc (16B) of rows lr, lr+32, ...
    const int lr = tid >> 3;            // 0..31
    const int lc = tid & 7;             // 0..7  (8 x 16B = 128B = BK row)
    const __nv_bfloat16* pA = A + (size_t)(row0 + lr) * KE + lc * 8;
    const __nv_bfloat16* pB = B + (size_t)(col0 + lr) * KE + lc * 8;
    const unsigned dA = (unsigned)(lr * 144 + lc * 16);
    const unsigned dB = A_BYTES + dA;

    wmma::fragment<wmma::accumulator, 16, 16, 16, float> acc[4][4];
#pragma unroll
    for (int i = 0; i < 4; i++)
#pragma unroll
        for (int j = 0; j < 4; j++) wmma::fill_fragment(acc[i][j], 0.0f);

    // prologue: stages 0,1
#pragma unroll
    for (int s = 0; s < 2; s++) {
        unsigned st = sb + s * STAGE_BYTES;
#pragma unroll
        for (int i = 0; i < 4; i++)
            CP_ASYNC16(st + dA + i * (32 * 144), pA + (size_t)i * 32 * KE);
#pragma unroll
        for (int i = 0; i < 8; i++)
            CP_ASYNC16(st + dB + i * (32 * 144), pB + (size_t)i * 32 * KE);
        CP_COMMIT();
        pA += BK; pB += BK;
    }

    const int niter = KE / BK;          // 192
    int cs_ = 0;                        // compute stage
    int ps_ = 2;                        // prefetch stage
    for (int kt = 0; kt < niter; kt++) {
        if (kt == niter - 1) { CP_WAIT(0); } else { CP_WAIT(1); }
        __syncthreads();

        if (kt + 2 < niter) {
            unsigned st = sb + ps_ * STAGE_BYTES;
#pragma unroll
            for (int i = 0; i < 4; i++)
                CP_ASYNC16(st + dA + i * (32 * 144), pA + (size_t)i * 32 * KE);
#pragma unroll
            for (int i = 0; i < 8; i++)
                CP_ASYNC16(st + dB + i * (32 * 144), pB + (size_t)i * 32 * KE);
            CP_COMMIT();
            pA += BK; pB += BK;
            ps_ = (ps_ == 2) ? 0 : ps_ + 1;
        }

        const __nv_bfloat16* sA =
            (const __nv_bfloat16*)(dsm + cs_ * STAGE_BYTES) + (wm * 64) * ASTRIDE;
        const __nv_bfloat16* sB =
            (const __nv_bfloat16*)(dsm + cs_ * STAGE_BYTES + A_BYTES) + (wn * 64) * ASTRIDE;
#pragma unroll
        for (int ks = 0; ks < 4; ks++) {
            wmma::fragment<wmma::matrix_a, 16, 16, 16, __nv_bfloat16, wmma::row_major> af[4];
            wmma::fragment<wmma::matrix_b, 16, 16, 16, __nv_bfloat16, wmma::col_major> bf[4];
#pragma unroll
            for (int i = 0; i < 4; i++)
                wmma::load_matrix_sync(af[i], sA + (i * 16) * ASTRIDE + ks * 16, ASTRIDE);
#pragma unroll
            for (int j = 0; j < 4; j++)
                wmma::load_matrix_sync(bf[j], sB + (j * 16) * ASTRIDE + ks * 16, ASTRIDE);
#pragma unroll
            for (int i = 0; i < 4; i++)
#pragma unroll
                for (int j = 0; j < 4; j++)
                    wmma::mma_sync(acc[i][j], af[i], bf[j], acc[i][j]);
        }
        cs_ = (cs_ == 2) ? 0 : cs_ + 1;
    }

    // ---- epilogue: stage accs through smem, fuse bias (+rope) ----
    __syncthreads();
    float* cbuf = (float*)dsm;
#pragma unroll
    for (int i = 0; i < 4; i++)
#pragma unroll
        for (int j = 0; j < 4; j++)
            wmma::store_matrix_sync(cbuf + (wm * 64 + i * 16) * CSTRIDE + wn * 64 + j * 16,
                                    acc[i][j], CSTRIDE, wmma::mem_row_major);
    __syncthreads();

#pragma unroll 4
    for (int q = 0; q < 32; q++) {
        int lin = tid + q * 256;        // 8192 float4 slots
        int r   = lin >> 6;
        int col = (lin & 63) * 4;
        float4 v = *(float4*)(cbuf + r * CSTRIDE + col);
        int grow = row0 + r;
        int gcol = col0 + col;
        if (mode == 0) {
            v.x += b0p[gcol];     v.y += b0p[gcol + 1];
            v.z += b0p[gcol + 2]; v.w += b0p[gcol + 3];
        } else {
            const float* bias = (gcol < 4096) ? b0p : (gcol < 8192) ? b1p : b2p;
            int nb = gcol & 4095;
            v.x += bias[nb];     v.y += bias[nb + 1];
            v.z += bias[nb + 2]; v.w += bias[nb + 3];
            if (gcol < 8192) {                 // rope on q,k
                int s = grow & 63, b = grow >> 6;
                int mp = s * 32 + ((gcol & 63) >> 1);
                float2 sc0 = g_rope[b * 2048 + mp];
                float2 sc1 = g_rope[b * 2048 + mp + 1];
                float rx = v.x * sc0.x - v.y * sc0.y;
                float ry = v.x * sc0.y + v.y * sc0.x;
                float rz = v.z * sc1.x - v.w * sc1.y;
                float rw = v.z * sc1.y + v.w * sc1.x;
                v = make_float4(rx, ry, rz, rw);
            }
        }
        *(float4*)(C + (size_t)grow * Ndim + gcol) = v;
    }
}

__global__ __launch_bounds__(256, 1) void gemm1_kernel(const float* __restrict__ bq,
                                                       const float* __restrict__ bk,
                                                       const float* __restrict__ bv) {
    gemm_core(g_Xext, g_Wqkv, g_QKV, TOK, NQKV, 1, bq, bk, bv);
}
__global__ __launch_bounds__(256, 1) void gemm2_kernel(float* __restrict__ out,
                                                       const float* __restrict__ bo) {
    gemm_core(g_Attext, g_Wo, out, TOK, D_MODEL, 0, bo, bo, bo);
}

// ---------------------------------------------------------------------------
// Attention: one CTA per (b,h). 64x64 tiles, fp32, smem softmax.
// Epilogue writes merged-head output directly in ext bf16 [hi|hi|lo] layout.
// ---------------------------------------------------------------------------
__global__ __launch_bounds__(256) void attn_kernel() {
    __shared__ __align__(16) float bufA[64][68];   // Q -> V -> O
    __shared__ __align__(16) float bufB[64][68];   // K -> S (exp weights)
    __shared__ float red1[256];
    __shared__ float red2[256];

    const int tid = threadIdx.x;
    const int bh  = blockIdx.x;
    const int b   = bh >> 6, h = bh & 63;
    const int rowbase = b << 6;
    const size_t qoff = (size_t)rowbase * NQKV + (h << 6);

#pragma unroll
    for (int it = 0; it < 4; ++it) {
        int i = tid + it * 256;
        int r = i >> 4, seg = i & 15;
        *(float4*)&bufA[r][seg * 4] = *(const float4*)&g_QKV[qoff + (size_t)r * NQKV + seg * 4];
        *(float4*)&bufB[r][seg * 4] = *(const float4*)&g_QKV[qoff + 4096 + (size_t)r * NQKV + seg * 4];
    }
    __syncthreads();

    const int r  = tid & 63;
    const int cg = tid >> 6;

    float acc[16];
#pragma unroll
    for (int c = 0; c < 16; c++) acc[c] = 0.0f;
    for (int d4 = 0; d4 < 16; ++d4) {
        float4 qv = *(float4*)&bufA[r][d4 * 4];
#pragma unroll
        for (int c = 0; c < 16; c++) {
            float4 kv = *(float4*)&bufB[cg * 16 + c][d4 * 4];
            acc[c] += qv.x * kv.x + qv.y * kv.y + qv.z * kv.z + qv.w * kv.w;
        }
    }
    __syncthreads();

    float lm = -1e30f;
#pragma unroll
    for (int c = 0; c < 16; c++) { acc[c] *= 0.125f; lm = fmaxf(lm, acc[c]); }
    red1[r * 4 + cg] = lm;
#pragma unroll
    for (int it = 0; it < 4; ++it) {
        int i = tid + it * 256;
        int rr = i >> 4, seg = i & 15;
        *(float4*)&bufA[rr][seg * 4] =
            *(const float4*)&g_QKV[qoff + 8192 + (size_t)rr * NQKV + seg * 4];
    }
    __syncthreads();

    float rmax = fmaxf(fmaxf(red1[r * 4 + 0], red1[r * 4 + 1]),
                       fmaxf(red1[r * 4 + 2], red1[r * 4 + 3]));
    float ls = 0.0f;
#pragma unroll
    for (int c = 0; c < 16; c++) {
        float e = __expf(acc[c] - rmax);
        bufB[r][cg * 16 + c] = e;
        ls += e;
    }
    red2[r * 4 + cg] = ls;
    __syncthreads();
    float inv = 1.0f / (red2[r * 4 + 0] + red2[r * 4 + 1] + red2[r * 4 + 2] + red2[r * 4 + 3]);

    float o[16];
#pragma unroll
    for (int c = 0; c < 16; c++) o[c] = 0.0f;
#pragma unroll 8
    for (int k = 0; k < 64; k++) {
        float p = bufB[r][k];
        float4 v0 = *(float4*)&bufA[k][cg * 16 + 0];
        float4 v1 = *(float4*)&bufA[k][cg * 16 + 4];
        float4 v2 = *(float4*)&bufA[k][cg * 16 + 8];
        float4 v3 = *(float4*)&bufA[k][cg * 16 + 12];
        o[0] += p * v0.x;  o[1] += p * v0.y;  o[2]  += p * v0.z;  o[3]  += p * v0.w;
        o[4] += p * v1.x;  o[5] += p * v1.y;  o[6]  += p * v1.z;  o[7]  += p * v1.w;
        o[8] += p * v2.x;  o[9] += p * v2.y;  o[10] += p * v2.z;  o[11] += p * v2.w;
        o[12]+= p * v3.x;  o[13]+= p * v3.y;  o[14] += p * v3.z;  o[15] += p * v3.w;
    }
    __syncthreads();
#pragma unroll
    for (int c = 0; c < 16; c++) bufA[r][cg * 16 + c] = o[c] * inv;
    __syncthreads();

    {
        int rr = tid >> 2, seg = tid & 3;
        const float* src = &bufA[rr][seg * 16];
        __align__(16) __nv_bfloat16 hi[16];
        __align__(16) __nv_bfloat16 lo[16];
#pragma unroll
        for (int t = 0; t < 16; t++) {
            float v = src[t];
            __nv_bfloat16 hh = __float2bfloat16(v);
            hi[t] = hh;
            lo[t] = __float2bfloat16(v - __bfloat162float(hh));
        }
        size_t base = (size_t)(rowbase + rr) * KE + (h << 6) + seg * 16;
        const uint4* ph = (const uint4*)hi;
        const uint4* pl = (const uint4*)lo;
        *(uint4*)&g_Attext[base]           = ph[0];
        *(uint4*)&g_Attext[base + 8]       = ph[1];
        *(uint4*)&g_Attext[base + 4096]    = ph[0];
        *(uint4*)&g_Attext[base + 4104]    = ph[1];
        *(uint4*)&g_Attext[base + 8192]    = pl[0];
        *(uint4*)&g_Attext[base + 8200]    = pl[1];
    }
}

// ---------------------------------------------------------------------------
// Launch
// ---------------------------------------------------------------------------
extern "C" void kernel_launch(void* const* d_in, const int* in_sizes, int n_in,
                              void* d_out, int out_size) {
    const float* x  = (const float*)d_in[0];
    const float* wq = (const float*)d_in[1];
    const float* bq = (const float*)d_in[2];
    const float* wk = (const float*)d_in[3];
    const float* bk = (const float*)d_in[4];
    const float* wv = (const float*)d_in[5];
    const float* bv = (const float*)d_in[6];
    const float* wo = (const float*)d_in[7];
    const float* bo = (const float*)d_in[8];
    float* out = (float*)d_out;

    cudaFuncSetAttribute(gemm1_kernel, cudaFuncAttributeMaxDynamicSharedMemorySize, SMEM_DYN);
    cudaFuncSetAttribute(gemm2_kernel, cudaFuncAttributeMaxDynamicSharedMemorySize, SMEM_DYN);

    conv_x_kernel   <<<65536, 256>>>(x);
    conv_wqkv_kernel<<<196608, 256>>>(wq, wk, wv);
    conv_wo_kernel  <<<65536, 256>>>(wo);
    rope_init_kernel<<<512, 256>>>();

    // gemm1: QKV = Xext @ Wqkv^T  (+bias, +rope fused)
    gemm1_kernel<<<(TOK / BM) * (NQKV / BN), 256, SMEM_DYN>>>(bq, bk, bv);

    attn_kernel<<<4096, 256>>>();

    // gemm2: out = Attext @ Wo^T + bo
    gemm2_kernel<<<(TOK / BM) * (D_MODEL / BN), 256, SMEM_DYN>>>(out, bo);
}

// round 16
// speedup vs baseline: 3.6693x; 3.1146x over previous
#include <cuda_runtime.h>
#include <cuda_fp16.h>
#include <mma.h>
#include <cstdint>

using namespace nvcuda;

// ---------------------------------------------------------------------------
// Problem constants
// ---------------------------------------------------------------------------
#define D_MODEL 4096
#define TOK     4096          // B*S = 64*64
#define NQKV    12288         // q|k|v concatenated output features

// ---------------------------------------------------------------------------
// Device scratch (static allocation: harness forbids cudaMalloc).
// NOTE: these symbols are referenced ONLY from device code — passing their
// address from host code is UB and was the R15 bug.
// ---------------------------------------------------------------------------
__device__ __align__(16) __half  g_X   [TOK * D_MODEL];                   //  32 MB
__device__ __align__(16) __half  g_W1  [NQKV * D_MODEL];                  //  96 MB (wq|wk|wv rows)
__device__ __align__(16) __half  g_W2  [D_MODEL * D_MODEL];               //  32 MB
__device__ __align__(16) float   g_QKV [TOK * NQKV];                      // 192 MB
__device__ __align__(16) __half  g_Att [TOK * D_MODEL];                   //  32 MB
__device__ __align__(16) float2  g_rope[64 * 2048];                       //   1 MB cos/sin

// ---------------------------------------------------------------------------
// helpers
// ---------------------------------------------------------------------------
__device__ __forceinline__ unsigned smem_u32(const void* p) {
    unsigned a;
    asm("{ .reg .u64 t; cvta.to.shared.u64 t, %1; cvt.u32.u64 %0, t; }"
        : "=r"(a) : "l"(p));
    return a;
}
#define CP_ASYNC16(dst, src) asm volatile("cp.async.cg.shared.global [%0], [%1], 16;" :: "r"(dst), "l"(src))
#define CP_COMMIT()          asm volatile("cp.async.commit_group;" ::: "memory")
#define CP_WAIT(n)           asm volatile("cp.async.wait_group %0;" :: "n"(n) : "memory")

union H2U { __half2 h; unsigned u; };

// ---------------------------------------------------------------------------
// Fused fp32 -> fp16 conversion for all five operand matrices.
// i indexes 8-element chunks; sel picks {x, wq, wk, wv, wo}; destinations are
// the device globals, addressed from device code.
// ---------------------------------------------------------------------------
__global__ void conv_all_kernel(const float* __restrict__ x,
                                const float* __restrict__ wq,
                                const float* __restrict__ wk,
                                const float* __restrict__ wv,
                                const float* __restrict__ wo) {
    int i   = blockIdx.x * blockDim.x + threadIdx.x;   // 0 .. 5*2^21-1
    int sel = i >> 21;                                  // 2^21 chunks = 2^24 elems
    int j   = i & 0x1FFFFF;                             // chunk within matrix

    const float* src;
    __half* dst;
    switch (sel) {
        case 0:  src = x;  dst = g_X;                                    break;
        case 1:  src = wq; dst = g_W1;                                   break;
        case 2:  src = wk; dst = g_W1 + (size_t)D_MODEL * D_MODEL;       break;
        case 3:  src = wv; dst = g_W1 + (size_t)2 * D_MODEL * D_MODEL;   break;
        default: src = wo; dst = g_W2;                                   break;
    }

    float4 a = ((const float4*)src)[2 * j];
    float4 b = ((const float4*)src)[2 * j + 1];
    H2U u0, u1, u2, u3;
    u0.h = __floats2half2_rn(a.x, a.y);
    u1.h = __floats2half2_rn(a.z, a.w);
    u2.h = __floats2half2_rn(b.x, b.y);
    u3.h = __floats2half2_rn(b.z, b.w);
    ((uint4*)dst)[j] = make_uint4(u0.u, u1.u, u2.u, u3.u);
}

// ---------------------------------------------------------------------------
// Rope table: theta(b, mp) = b * 10000^(-mp/2048);  g_rope = (cos, sin)
// ---------------------------------------------------------------------------
__global__ void rope_init_kernel() {
    int i  = blockIdx.x * blockDim.x + threadIdx.x;     // 131072
    int b  = i >> 11, mp = i & 2047;
    float invf = exp2f(-(float)mp * (13.287712379549449f / 2048.0f));
    float sn, cs;
    sincosf((float)b * invf, &sn, &cs);
    g_rope[i] = make_float2(cs, sn);
}

// ---------------------------------------------------------------------------
// wmma fp16 GEMM: C[M][N] = A[M][K]*B[N][K]^T, fp32 acc, K = 4096.
// CTA tile 128x256, BK=64, 3-stage cp.async pipeline, 8 warps each 64x64.
// mode 1: fused bias + table-rope (QKV);  mode 0: fused bias (out proj).
// ---------------------------------------------------------------------------
#define BM 128
#define BN 256
#define BK 64
#define KDIM 4096
#define ASTRIDE 72                               // padded row: 72 half = 144 B
#define A_BYTES (BM * ASTRIDE * 2)               // 18432
#define B_BYTES (BN * ASTRIDE * 2)               // 36864
#define STAGE_BYTES (A_BYTES + B_BYTES)          // 55296
#define NST 3
#define SMEM_DYN (NST * STAGE_BYTES)             // 165888 (162 KB)
#define CSTRIDE 260                              // fp32 epilogue buffer stride

__device__ __forceinline__ void gemm_core(
    const __half* __restrict__ A, const __half* __restrict__ B,
    float* __restrict__ C, int Mdim, int Ndim, int mode,
    const float* __restrict__ b0p, const float* __restrict__ b1p,
    const float* __restrict__ b2p)
{
    extern __shared__ char dsm[];
    const unsigned sb = smem_u32(dsm);
    const int tid  = threadIdx.x;
    const int warp = tid >> 5;
    const int wm   = warp & 1;          // 0..1 : 64-row group
    const int wn   = warp >> 1;         // 0..3 : 64-col group

    // grouped rasterization along M (keeps B panels hot in L2)
    const int num_n = Ndim >> 8;
    const int num_m = Mdim >> 7;
    const int GROUP = 16;
    int per   = GROUP * num_n;
    int gid   = blockIdx.x / per;
    int rem   = blockIdx.x % per;
    int first = gid * GROUP;
    int gsz   = min(GROUP, num_m - first);
    int pm    = first + rem % gsz;
    int pn    = rem / gsz;
    const int row0 = pm << 7, col0 = pn << 8;

    // cp.async mapping: thread owns col-chunk lc (16B) of rows lr, lr+32, ...
    const int lr = tid >> 3;            // 0..31
    const int lc = tid & 7;             // 0..7  (8 x 16B = 128B = BK row)
    const __half* pA = A + (size_t)(row0 + lr) * KDIM + lc * 8;
    const __half* pB = B + (size_t)(col0 + lr) * KDIM + lc * 8;
    const unsigned dA = (unsigned)(lr * 144 + lc * 16);
    const unsigned dB = A_BYTES + dA;

    wmma::fragment<wmma::accumulator, 16, 16, 16, float> acc[4][4];
#pragma unroll
    for (int i = 0; i < 4; i++)
#pragma unroll
        for (int j = 0; j < 4; j++) wmma::fill_fragment(acc[i][j], 0.0f);

    // prologue: stages 0,1
#pragma unroll
    for (int s = 0; s < 2; s++) {
        unsigned st = sb + s * STAGE_BYTES;
#pragma unroll
        for (int i = 0; i < 4; i++)
            CP_ASYNC16(st + dA + i * (32 * 144), pA + (size_t)i * 32 * KDIM);
#pragma unroll
        for (int i = 0; i < 8; i++)
            CP_ASYNC16(st + dB + i * (32 * 144), pB + (size_t)i * 32 * KDIM);
        CP_COMMIT();
        pA += BK; pB += BK;
    }

    const int niter = KDIM / BK;        // 64
    int cs_ = 0;                        // compute stage
    int ps_ = 2;                        // prefetch stage
    for (int kt = 0; kt < niter; kt++) {
        if (kt == niter - 1) { CP_WAIT(0); } else { CP_WAIT(1); }
        __syncthreads();

        if (kt + 2 < niter) {
            unsigned st = sb + ps_ * STAGE_BYTES;
#pragma unroll
            for (int i = 0; i < 4; i++)
                CP_ASYNC16(st + dA + i * (32 * 144), pA + (size_t)i * 32 * KDIM);
#pragma unroll
            for (int i = 0; i < 8; i++)
                CP_ASYNC16(st + dB + i * (32 * 144), pB + (size_t)i * 32 * KDIM);
            CP_COMMIT();
            pA += BK; pB += BK;
            ps_ = (ps_ == 2) ? 0 : ps_ + 1;
        }

        const __half* sA =
            (const __half*)(dsm + cs_ * STAGE_BYTES) + (wm * 64) * ASTRIDE;
        const __half* sB =
            (const __half*)(dsm + cs_ * STAGE_BYTES + A_BYTES) + (wn * 64) * ASTRIDE;
#pragma unroll
        for (int ks = 0; ks < 4; ks++) {
            wmma::fragment<wmma::matrix_a, 16, 16, 16, __half, wmma::row_major> af[4];
            wmma::fragment<wmma::matrix_b, 16, 16, 16, __half, wmma::col_major> bf[4];
#pragma unroll
            for (int i = 0; i < 4; i++)
                wmma::load_matrix_sync(af[i], sA + (i * 16) * ASTRIDE + ks * 16, ASTRIDE);
#pragma unroll
            for (int j = 0; j < 4; j++)
                wmma::load_matrix_sync(bf[j], sB + (j * 16) * ASTRIDE + ks * 16, ASTRIDE);
#pragma unroll
            for (int i = 0; i < 4; i++)
#pragma unroll
                for (int j = 0; j < 4; j++)
                    wmma::mma_sync(acc[i][j], af[i], bf[j], acc[i][j]);
        }
        cs_ = (cs_ == 2) ? 0 : cs_ + 1;
    }

    // ---- epilogue: stage accs through smem, fuse bias (+rope) ----
    __syncthreads();
    float* cbuf = (float*)dsm;
#pragma unroll
    for (int i = 0; i < 4; i++)
#pragma unroll
        for (int j = 0; j < 4; j++)
            wmma::store_matrix_sync(cbuf + (wm * 64 + i * 16) * CSTRIDE + wn * 64 + j * 16,
                                    acc[i][j], CSTRIDE, wmma::mem_row_major);
    __syncthreads();

#pragma unroll 4
    for (int q = 0; q < 32; q++) {
        int lin = tid + q * 256;        // 8192 float4 slots
        int r   = lin >> 6;
        int col = (lin & 63) * 4;
        float4 v = *(float4*)(cbuf + r * CSTRIDE + col);
        int grow = row0 + r;
        int gcol = col0 + col;
        if (mode == 0) {
            v.x += b0p[gcol];     v.y += b0p[gcol + 1];
            v.z += b0p[gcol + 2]; v.w += b0p[gcol + 3];
        } else {
            const float* bias = (gcol < 4096) ? b0p : (gcol < 8192) ? b1p : b2p;
            int nb = gcol & 4095;
            v.x += bias[nb];     v.y += bias[nb + 1];
            v.z += bias[nb + 2]; v.w += bias[nb + 3];
            if (gcol < 8192) {                 // rope on q,k (pos = batch quirk)
                int s = grow & 63, b = grow >> 6;
                int mp = s * 32 + ((gcol & 63) >> 1);
                float2 sc0 = g_rope[b * 2048 + mp];
                float2 sc1 = g_rope[b * 2048 + mp + 1];
                float rx = v.x * sc0.x - v.y * sc0.y;
                float ry = v.x * sc0.y + v.y * sc0.x;
                float rz = v.z * sc1.x - v.w * sc1.y;
                float rw = v.z * sc1.y + v.w * sc1.x;
                v = make_float4(rx, ry, rz, rw);
            }
        }
        *(float4*)(C + (size_t)grow * Ndim + gcol) = v;
    }
}

__global__ __launch_bounds__(256, 1) void gemm1_kernel(const float* __restrict__ bq,
                                                       const float* __restrict__ bk,
                                                       const float* __restrict__ bv) {
    gemm_core(g_X, g_W1, g_QKV, TOK, NQKV, 1, bq, bk, bv);
}
__global__ __launch_bounds__(256, 1) void gemm2_kernel(float* __restrict__ out,
                                                       const float* __restrict__ bo) {
    gemm_core(g_Att, g_W2, out, TOK, D_MODEL, 0, bo, bo, bo);
}

// ---------------------------------------------------------------------------
// Attention: one CTA per (b,h). 64x64 tiles, fp32, smem softmax.
// Epilogue writes merged-head output as fp16 (gemm2 operand layout).
// ---------------------------------------------------------------------------
__global__ __launch_bounds__(256) void attn_kernel() {
    __shared__ __align__(16) float bufA[64][68];   // Q -> V -> O
    __shared__ __align__(16) float bufB[64][68];   // K -> S (exp weights)
    __shared__ float red1[256];
    __shared__ float red2[256];

    const int tid = threadIdx.x;
    const int bh  = blockIdx.x;
    const int b   = bh >> 6, h = bh & 63;
    const int rowbase = b << 6;
    const size_t qoff = (size_t)rowbase * NQKV + (h << 6);

#pragma unroll
    for (int it = 0; it < 4; ++it) {
        int i = tid + it * 256;
        int r = i >> 4, seg = i & 15;
        *(float4*)&bufA[r][seg * 4] = *(const float4*)&g_QKV[qoff + (size_t)r * NQKV + seg * 4];
        *(float4*)&bufB[r][seg * 4] = *(const float4*)&g_QKV[qoff + 4096 + (size_t)r * NQKV + seg * 4];
    }
    __syncthreads();

    const int r  = tid & 63;
    const int cg = tid >> 6;

    float acc[16];
#pragma unroll
    for (int c = 0; c < 16; c++) acc[c] = 0.0f;
    for (int d4 = 0; d4 < 16; ++d4) {
        float4 qv = *(float4*)&bufA[r][d4 * 4];
#pragma unroll
        for (int c = 0; c < 16; c++) {
            float4 kv = *(float4*)&bufB[cg * 16 + c][d4 * 4];
            acc[c] += qv.x * kv.x + qv.y * kv.y + qv.z * kv.z + qv.w * kv.w;
        }
    }
    __syncthreads();

    float lm = -1e30f;
#pragma unroll
    for (int c = 0; c < 16; c++) { acc[c] *= 0.125f; lm = fmaxf(lm, acc[c]); }
    red1[r * 4 + cg] = lm;
#pragma unroll
    for (int it = 0; it < 4; ++it) {
        int i = tid + it * 256;
        int rr = i >> 4, seg = i & 15;
        *(float4*)&bufA[rr][seg * 4] =
            *(const float4*)&g_QKV[qoff + 8192 + (size_t)rr * NQKV + seg * 4];
    }
    __syncthreads();

    float rmax = fmaxf(fmaxf(red1[r * 4 + 0], red1[r * 4 + 1]),
                       fmaxf(red1[r * 4 + 2], red1[r * 4 + 3]));
    float ls = 0.0f;
#pragma unroll
    for (int c = 0; c < 16; c++) {
        float e = __expf(acc[c] - rmax);
        bufB[r][cg * 16 + c] = e;
        ls += e;
    }
    red2[r * 4 + cg] = ls;
    __syncthreads();
    float inv = 1.0f / (red2[r * 4 + 0] + red2[r * 4 + 1] + red2[r * 4 + 2] + red2[r * 4 + 3]);

    float o[16];
#pragma unroll
    for (int c = 0; c < 16; c++) o[c] = 0.0f;
#pragma unroll 8
    for (int k = 0; k < 64; k++) {
        float p = bufB[r][k];
        float4 v0 = *(float4*)&bufA[k][cg * 16 + 0];
        float4 v1 = *(float4*)&bufA[k][cg * 16 + 4];
        float4 v2 = *(float4*)&bufA[k][cg * 16 + 8];
        float4 v3 = *(float4*)&bufA[k][cg * 16 + 12];
        o[0] += p * v0.x;  o[1] += p * v0.y;  o[2]  += p * v0.z;  o[3]  += p * v0.w;
        o[4] += p * v1.x;  o[5] += p * v1.y;  o[6]  += p * v1.z;  o[7]  += p * v1.w;
        o[8] += p * v2.x;  o[9] += p * v2.y;  o[10] += p * v2.z;  o[11] += p * v2.w;
        o[12]+= p * v3.x;  o[13]+= p * v3.y;  o[14] += p * v3.z;  o[15] += p * v3.w;
    }
    __syncthreads();
#pragma unroll
    for (int c = 0; c < 16; c++) bufA[r][cg * 16 + c] = o[c] * inv;
    __syncthreads();

    // fp16 epilogue: merged-head row, 16 half per thread (two uint4 stores)
    {
        int rr = tid >> 2, seg = tid & 3;
        const float* src = &bufA[rr][seg * 16];
        H2U u[8];
#pragma unroll
        for (int t = 0; t < 8; t++)
            u[t].h = __floats2half2_rn(src[2 * t], src[2 * t + 1]);
        size_t base = (size_t)(rowbase + rr) * D_MODEL + (h << 6) + seg * 16;
        *(uint4*)&g_Att[base]     = make_uint4(u[0].u, u[1].u, u[2].u, u[3].u);
        *(uint4*)&g_Att[base + 8] = make_uint4(u[4].u, u[5].u, u[6].u, u[7].u);
    }
}

// ---------------------------------------------------------------------------
// Launch
// ---------------------------------------------------------------------------
extern "C" void kernel_launch(void* const* d_in, const int* in_sizes, int n_in,
                              void* d_out, int out_size) {
    const float* x  = (const float*)d_in[0];
    const float* wq = (const float*)d_in[1];
    const float* bq = (const float*)d_in[2];
    const float* wk = (const float*)d_in[3];
    const float* bk = (const float*)d_in[4];
    const float* wv = (const float*)d_in[5];
    const float* bv = (const float*)d_in[6];
    const float* wo = (const float*)d_in[7];
    const float* bo = (const float*)d_in[8];
    float* out = (float*)d_out;

    cudaFuncSetAttribute(gemm1_kernel, cudaFuncAttributeMaxDynamicSharedMemorySize, SMEM_DYN);
    cudaFuncSetAttribute(gemm2_kernel, cudaFuncAttributeMaxDynamicSharedMemorySize, SMEM_DYN);

    // fp32 -> fp16 conversion of all five operand matrices (5 * 2^21 chunks)
    conv_all_kernel <<<40960, 256>>>(x, wq, wk, wv, wo);
    rope_init_kernel<<<512, 256>>>();

    // gemm1: QKV = X @ W1^T  (+bias, +rope fused)   grid 32x48
    gemm1_kernel<<<(TOK / BM) * (NQKV / BN), 256, SMEM_DYN>>>(bq, bk, bv);

    attn_kernel<<<4096, 256>>>();

    // gemm2: out = Att @ W2^T + bo                  grid 32x16
    gemm2_kernel<<<(TOK / BM) * (D_MODEL / BN), 256, SMEM_DYN>>>(out, bo);
}